// round 1
// baseline (speedup 1.0000x reference)
#include <cuda_runtime.h>

#define LSEQ   2048
#define BATCH  32
#define TPB    256
#define NCHUNK 4          // NCHUNK * TPB == LSEQ / 2
#define DT_C   0.01f
#define EPS_C  1e-5f

// exp(x) via single MUFU.EX2 with log2(e) folded into the query scale upstream.
__device__ __forceinline__ float ex2f(float x) {
    float y;
    asm("ex2.approx.ftz.f32 %0, %1;" : "=f"(y) : "f"(x));
    return y;
}

__global__ void __launch_bounds__(TPB)
ac_filter_kernel(const float* __restrict__ inp,        // [B, L, 3]
                 const float* __restrict__ ipw,        // [9, 3]
                 const float* __restrict__ ipb,        // [9]
                 const float* __restrict__ opw,        // [3, 3]
                 const float* __restrict__ opb,        // [3]
                 const float* __restrict__ f1w, const float* __restrict__ f1b,
                 const float* __restrict__ f2w, const float* __restrict__ f2b,
                 const float* __restrict__ g1w, const float* __restrict__ g1b,
                 const float* __restrict__ g2w, const float* __restrict__ g2b,
                 const float* __restrict__ m1p, const float* __restrict__ m2p,
                 const float* __restrict__ sig,
                 float* __restrict__ out)               // [B, L, 8]
{
    extern __shared__ float4 sm[];
    float4* ks = sm;          // [LSEQ] keys   (x,y,z,pad)
    float4* vs = sm + LSEQ;   // [LSEQ] values

    const int b = blockIdx.x;
    const int c = blockIdx.y;
    const int t = threadIdx.x;

    const float sc0 = __ldg(&sig[0]) + EPS_C;
    const float sc1 = __ldg(&sig[1]) + EPS_C;
    const float inv_sc0 = 1.0f / sc0;
    const float inv_sc1 = 1.0f / sc1;

    // ---- K/V weights (rows 3..5 and 6..8 of in_proj) ----
    float wk[9], wv[9], bk[3], bv[3];
    #pragma unroll
    for (int i = 0; i < 9; i++) { wk[i] = __ldg(&ipw[9 + i]);  wv[i] = __ldg(&ipw[18 + i]); }
    #pragma unroll
    for (int i = 0; i < 3; i++) { bk[i] = __ldg(&ipb[3 + i]);  bv[i] = __ldg(&ipb[6 + i]); }

    const float* xb = inp + (size_t)b * LSEQ * 3;

    // ---- stage K, V for the whole batch row into smem ----
    for (int j = t; j < LSEQ; j += TPB) {
        float x0 = xb[j * 3 + 0];
        float x1 = xb[j * 3 + 1] * inv_sc0;
        float x2 = xb[j * 3 + 2] * inv_sc1;
        float k0 = fmaf(wk[0], x0, fmaf(wk[1], x1, fmaf(wk[2], x2, bk[0])));
        float k1 = fmaf(wk[3], x0, fmaf(wk[4], x1, fmaf(wk[5], x2, bk[1])));
        float k2 = fmaf(wk[6], x0, fmaf(wk[7], x1, fmaf(wk[8], x2, bk[2])));
        float v0 = fmaf(wv[0], x0, fmaf(wv[1], x1, fmaf(wv[2], x2, bv[0])));
        float v1 = fmaf(wv[3], x0, fmaf(wv[4], x1, fmaf(wv[5], x2, bv[1])));
        float v2 = fmaf(wv[6], x0, fmaf(wv[7], x1, fmaf(wv[8], x2, bv[2])));
        ks[j] = make_float4(k0, k1, k2, 0.0f);
        vs[j] = make_float4(v0, v1, v2, 0.0f);
    }

    // ---- queries: pair (qa, L-1-qa) so per-thread key work is constant ----
    const int qa = c * TPB + t;        // 0 .. 1023
    const int qb = LSEQ - 1 - qa;      // 1024 .. 2047  (qb > qa always)

    // score = dot(q,k)/sqrt(3); exp(score) = exp2(dot * log2e/sqrt(3))
    const float QS = 1.4426950408889634f * 0.57735026918962576f;

    float wq[9], bq[3];
    #pragma unroll
    for (int i = 0; i < 9; i++) wq[i] = __ldg(&ipw[i]);
    #pragma unroll
    for (int i = 0; i < 3; i++) bq[i] = __ldg(&ipb[i]);

    float qa0, qa1, qa2, qb0, qb1, qb2;
    {
        float x0 = xb[qa * 3 + 0], x1 = xb[qa * 3 + 1] * inv_sc0, x2 = xb[qa * 3 + 2] * inv_sc1;
        qa0 = fmaf(wq[0], x0, fmaf(wq[1], x1, fmaf(wq[2], x2, bq[0]))) * QS;
        qa1 = fmaf(wq[3], x0, fmaf(wq[4], x1, fmaf(wq[5], x2, bq[1]))) * QS;
        qa2 = fmaf(wq[6], x0, fmaf(wq[7], x1, fmaf(wq[8], x2, bq[2]))) * QS;
        float y0 = xb[qb * 3 + 0], y1 = xb[qb * 3 + 1] * inv_sc0, y2 = xb[qb * 3 + 2] * inv_sc1;
        qb0 = fmaf(wq[0], y0, fmaf(wq[1], y1, fmaf(wq[2], y2, bq[0]))) * QS;
        qb1 = fmaf(wq[3], y0, fmaf(wq[4], y1, fmaf(wq[5], y2, bq[1]))) * QS;
        qb2 = fmaf(wq[6], y0, fmaf(wq[7], y1, fmaf(wq[8], y2, bq[2]))) * QS;
    }

    __syncthreads();

    // ---- causal attention, one-pass (no max subtraction: |score| << 88) ----
    float sumA = 0.f, a0 = 0.f, a1 = 0.f, a2 = 0.f;
    float sumB = 0.f, e0 = 0.f, e1 = 0.f, e2 = 0.f;

    #pragma unroll 4
    for (int j = 0; j <= qb; j++) {
        float4 k = ks[j];
        float4 v = vs[j];
        float sa = fmaf(qa0, k.x, fmaf(qa1, k.y, qa2 * k.z));
        float sb = fmaf(qb0, k.x, fmaf(qb1, k.y, qb2 * k.z));
        float pa = (j <= qa) ? ex2f(sa) : 0.0f;
        float pb = ex2f(sb);
        sumA += pa; a0 = fmaf(pa, v.x, a0); a1 = fmaf(pa, v.y, a1); a2 = fmaf(pa, v.z, a2);
        sumB += pb; e0 = fmaf(pb, v.x, e0); e1 = fmaf(pb, v.y, e1); e2 = fmaf(pb, v.z, e2);
    }

    // ---- epilogue weights ----
    float wo[9], bo1, bo2;
    #pragma unroll
    for (int i = 0; i < 9; i++) wo[i] = __ldg(&opw[i]);
    bo1 = __ldg(&opb[1]); bo2 = __ldg(&opb[2]);
    const float m1 = __ldg(m1p), m2 = __ldg(m2p);
    float F1[3], F2[3], G1[3], G2[3];
    #pragma unroll
    for (int i = 0; i < 3; i++) {
        F1[i] = __ldg(&f1w[i]); F2[i] = __ldg(&f2w[i]);
        G1[i] = __ldg(&g1w[i]); G2[i] = __ldg(&g2w[i]);
    }
    const float F1b = __ldg(f1b), F2b = __ldg(f2b), G1b = __ldg(g1b), G2b = __ldg(g2b);

    // per-query epilogue: out-proj rows 1,2 only; s[0] == 1 throughout the chain.
    auto emit = [&](int q, float cs, float c0, float c1, float c2) {
        float inv = 1.0f / cs;
        float x0 = c0 * inv, x1 = c1 * inv, x2 = c2 * inv;   // ctx
        float s1 = fmaf(wo[3], x0, fmaf(wo[4], x1, fmaf(wo[5], x2, bo1)));  // attn[1]
        float s2 = fmaf(wo[6], x0, fmaf(wo[7], x1, fmaf(wo[8], x2, bo2)));  // attn[2]
        // S1 = [1, s1, s2]; three Euler steps with g-velocities
        float S2_1, S2_2, S3_1, S3_2, S4_1, S4_2;
        {
            float g1v = (G1[0] + fmaf(G1[1], s1, fmaf(G1[2], s2, G1b))) * m1;
            float g2v = (G2[0] + fmaf(G2[1], s1, fmaf(G2[2], s2, G2b))) * m2;
            S2_1 = fmaf(g1v, DT_C, s1); S2_2 = fmaf(g2v, DT_C, s2);
        }
        {
            float g1v = (G1[0] + fmaf(G1[1], S2_1, fmaf(G1[2], S2_2, G1b))) * m1;
            float g2v = (G2[0] + fmaf(G2[1], S2_1, fmaf(G2[2], S2_2, G2b))) * m2;
            S3_1 = fmaf(g1v, DT_C, S2_1); S3_2 = fmaf(g2v, DT_C, S2_2);
        }
        {
            float g1v = (G1[0] + fmaf(G1[1], S3_1, fmaf(G1[2], S3_2, G1b))) * m1;
            float g2v = (G2[0] + fmaf(G2[1], S3_1, fmaf(G2[2], S3_2, G2b))) * m2;
            S4_1 = fmaf(g1v, DT_C, S3_1); S4_2 = fmaf(g2v, DT_C, S3_2);
        }
        float vd1 = (F1[0] + fmaf(F1[1], S4_1, fmaf(F1[2], S4_2, F1b))) * m1;
        float vd2 = (F2[0] + fmaf(F2[1], S4_1, fmaf(F2[2], S4_2, F2b))) * m2;

        float4* o = (float4*)(out + (((size_t)b * LSEQ + q) << 3));
        o[0] = make_float4(S2_1 * sc0, S2_2 * sc1, S3_1 * sc0, S3_2 * sc1);
        o[1] = make_float4(S4_1 * sc0, S4_2 * sc1,
                           fmaf(vd1, DT_C, S4_1) * sc0, fmaf(vd2, DT_C, S4_2) * sc1);
    };

    emit(qa, sumA, a0, a1, a2);
    emit(qb, sumB, e0, e1, e2);
}

extern "C" void kernel_launch(void* const* d_in, const int* in_sizes, int n_in,
                              void* d_out, int out_size)
{
    // metadata order: t, inputs, in_proj_w, in_proj_b, out_proj_w, out_proj_b,
    //                 f1_w, f1_b, f2_w, f2_b, g1_w, g1_b, g2_w, g2_b, m1_s, m2_s, sigma
    const float* inp = (const float*)d_in[1];
    const float* ipw = (const float*)d_in[2];
    const float* ipb = (const float*)d_in[3];
    const float* opw = (const float*)d_in[4];
    const float* opb = (const float*)d_in[5];
    const float* f1w = (const float*)d_in[6];
    const float* f1b = (const float*)d_in[7];
    const float* f2w = (const float*)d_in[8];
    const float* f2b = (const float*)d_in[9];
    const float* g1w = (const float*)d_in[10];
    const float* g1b = (const float*)d_in[11];
    const float* g2w = (const float*)d_in[12];
    const float* g2b = (const float*)d_in[13];
    const float* m1p = (const float*)d_in[14];
    const float* m2p = (const float*)d_in[15];
    const float* sig = (const float*)d_in[16];
    float* out = (float*)d_out;

    const int smem = 2 * LSEQ * sizeof(float4);  // 64 KB
    cudaFuncSetAttribute(ac_filter_kernel, cudaFuncAttributeMaxDynamicSharedMemorySize, smem);

    dim3 grid(BATCH, NCHUNK);
    ac_filter_kernel<<<grid, TPB, smem>>>(inp, ipw, ipb, opw, opb,
                                          f1w, f1b, f2w, f2b,
                                          g1w, g1b, g2w, g2b,
                                          m1p, m2p, sig, out);
}

// round 3
// speedup vs baseline: 1.3182x; 1.3182x over previous
#include <cuda_runtime.h>

#define LSEQ    2048
#define BATCH   32
#define NPAIR   (LSEQ/2)        // 1024 key pairs per batch
#define TPB2    128
#define NCHUNK2 16              // TPB2 * NCHUNK2 == LSEQ
#define DT_C    0.01f
#define EPS_C   1e-5f
// exp(x) = exp2(x * log2e); fold log2e/sqrt(3) into query scale
#define QS_C    (1.4426950408889634f * 0.57735026918962576f)

typedef unsigned long long ull;

// ---------- f32x2 packed helpers (PTX ISA 8.6, sm_100+) ----------
__device__ __forceinline__ ull fma2(ull a, ull b, ull c) {
    ull d; asm("fma.rn.f32x2 %0, %1, %2, %3;" : "=l"(d) : "l"(a), "l"(b), "l"(c)); return d;
}
__device__ __forceinline__ ull mul2(ull a, ull b) {
    ull d; asm("mul.rn.f32x2 %0, %1, %2;" : "=l"(d) : "l"(a), "l"(b)); return d;
}
__device__ __forceinline__ ull add2(ull a, ull b) {
    ull d; asm("add.rn.f32x2 %0, %1, %2;" : "=l"(d) : "l"(a), "l"(b)); return d;
}
__device__ __forceinline__ ull pk2(float lo, float hi) {
    ull r; asm("mov.b64 %0, {%1, %2};" : "=l"(r) : "f"(lo), "f"(hi)); return r;
}
__device__ __forceinline__ void up2(ull v, float& lo, float& hi) {
    asm("mov.b64 {%0, %1}, %2;" : "=f"(lo), "=f"(hi) : "l"(v));
}
__device__ __forceinline__ float ex2f(float x) {
    float y; asm("ex2.approx.ftz.f32 %0, %1;" : "=f"(y) : "f"(x)); return y;
}

// ---------- scratch (no cudaMalloc allowed) ----------
__device__ float4 g_P[BATCH][NPAIR];   // (k0e, k0o, k1e, k1o)
__device__ float4 g_Q[BATCH][NPAIR];   // (k2e, k2o, v0e, v0o)
__device__ float4 g_R[BATCH][NPAIR];   // (v1e, v1o, v2e, v2o)
__device__ float4 g_QY[BATCH][LSEQ];   // (q0, q1, q2, 0) * QS

// ================= kernel 1: projection =================
__global__ void __launch_bounds__(256)
proj_kernel(const float* __restrict__ inp,
            const float* __restrict__ ipw, const float* __restrict__ ipb,
            const float* __restrict__ sig)
{
    int idx = blockIdx.x * 256 + threadIdx.x;        // one key pair
    if (idx >= BATCH * NPAIR) return;
    int b = idx >> 10, i = idx & (NPAIR - 1);
    int j0 = 2 * i, j1 = 2 * i + 1;

    const float inv0 = 1.0f / (__ldg(&sig[0]) + EPS_C);
    const float inv1 = 1.0f / (__ldg(&sig[1]) + EPS_C);

    float W[27], Bv[9];
    #pragma unroll
    for (int k = 0; k < 27; k++) W[k] = __ldg(&ipw[k]);
    #pragma unroll
    for (int k = 0; k < 9; k++)  Bv[k] = __ldg(&ipb[k]);

    const float* xb = inp + ((size_t)b * LSEQ) * 3;
    float xe0 = xb[j0*3+0], xe1 = xb[j0*3+1]*inv0, xe2 = xb[j0*3+2]*inv1;
    float xo0 = xb[j1*3+0], xo1 = xb[j1*3+1]*inv0, xo2 = xb[j1*3+2]*inv1;

    float qe[3], qo[3], ke[3], ko[3], ve[3], vo[3];
    #pragma unroll
    for (int r = 0; r < 3; r++) {
        qe[r] = fmaf(W[3*r+0], xe0, fmaf(W[3*r+1], xe1, fmaf(W[3*r+2], xe2, Bv[r])));
        qo[r] = fmaf(W[3*r+0], xo0, fmaf(W[3*r+1], xo1, fmaf(W[3*r+2], xo2, Bv[r])));
        ke[r] = fmaf(W[9+3*r+0], xe0, fmaf(W[9+3*r+1], xe1, fmaf(W[9+3*r+2], xe2, Bv[3+r])));
        ko[r] = fmaf(W[9+3*r+0], xo0, fmaf(W[9+3*r+1], xo1, fmaf(W[9+3*r+2], xo2, Bv[3+r])));
        ve[r] = fmaf(W[18+3*r+0], xe0, fmaf(W[18+3*r+1], xe1, fmaf(W[18+3*r+2], xe2, Bv[6+r])));
        vo[r] = fmaf(W[18+3*r+0], xo0, fmaf(W[18+3*r+1], xo1, fmaf(W[18+3*r+2], xo2, Bv[6+r])));
    }
    g_P[b][i] = make_float4(ke[0], ko[0], ke[1], ko[1]);
    g_Q[b][i] = make_float4(ke[2], ko[2], ve[0], vo[0]);
    g_R[b][i] = make_float4(ve[1], vo[1], ve[2], vo[2]);
    g_QY[b][j0] = make_float4(qe[0]*QS_C, qe[1]*QS_C, qe[2]*QS_C, 0.f);
    g_QY[b][j1] = make_float4(qo[0]*QS_C, qo[1]*QS_C, qo[2]*QS_C, 0.f);
}

// ================= kernel 2: attention + ODE epilogue =================
__global__ void __launch_bounds__(TPB2)
attn_kernel(const float* __restrict__ opw, const float* __restrict__ opb,
            const float* __restrict__ f1w, const float* __restrict__ f1b,
            const float* __restrict__ f2w, const float* __restrict__ f2b,
            const float* __restrict__ g1w, const float* __restrict__ g1b,
            const float* __restrict__ g2w, const float* __restrict__ g2b,
            const float* __restrict__ m1p, const float* __restrict__ m2p,
            const float* __restrict__ sig,
            float* __restrict__ out)
{
    extern __shared__ float4 sm[];
    float4* sP = sm;                // [NPAIR]
    float4* sQ = sm + NPAIR;
    float4* sR = sm + 2 * NPAIR;

    const int b = blockIdx.x;
    const int chunk = (NCHUNK2 - 1) - blockIdx.y;     // big blocks first (LPT)
    const int t = threadIdx.x;
    const int q = chunk * TPB2 + t;

    // stage only the causal prefix of key pairs this block needs
    const int npstage = chunk * (TPB2 / 2) + (TPB2 / 2);
    for (int i = t; i < npstage; i += TPB2) {
        sP[i] = g_P[b][i];
        sQ[i] = g_Q[b][i];
        sR[i] = g_R[b][i];
    }

    float4 qv = g_QY[b][q];

    // epilogue constants: load early to overlap with staging latency
    const float sc0 = __ldg(&sig[0]) + EPS_C;
    const float sc1 = __ldg(&sig[1]) + EPS_C;
    float wo[9];
    #pragma unroll
    for (int i = 0; i < 9; i++) wo[i] = __ldg(&opw[i]);
    const float bo1 = __ldg(&opb[1]), bo2 = __ldg(&opb[2]);
    const float m1 = __ldg(m1p), m2 = __ldg(m2p);
    float F1[3], F2[3], G1[3], G2[3];
    #pragma unroll
    for (int i = 0; i < 3; i++) {
        F1[i] = __ldg(&f1w[i]); F2[i] = __ldg(&f2w[i]);
        G1[i] = __ldg(&g1w[i]); G2[i] = __ldg(&g2w[i]);
    }
    const float F1b = __ldg(f1b), F2b = __ldg(f2b), G1b = __ldg(g1b), G2b = __ldg(g2b);

    __syncthreads();

    const ull qp0 = pk2(qv.x, qv.x);
    const ull qp1 = pk2(qv.y, qv.y);
    const ull qp2 = pk2(qv.z, qv.z);

    ull sum2 = 0ull, a02 = 0ull, a12 = 0ull, a22 = 0ull;  // (0.f, 0.f)
    const ulonglong2* pP = (const ulonglong2*)sP;
    const ulonglong2* pQ = (const ulonglong2*)sQ;
    const ulonglong2* pR = (const ulonglong2*)sR;

    const int np = (q + 1) >> 1;          // full key pairs
    #pragma unroll 4
    for (int i = 0; i < np; i++) {
        ulonglong2 Pv = pP[i];            // .x=(k0e,k0o) .y=(k1e,k1o)
        ulonglong2 Qv = pQ[i];            // .x=(k2e,k2o) .y=(v0e,v0o)
        ulonglong2 Rv = pR[i];            // .x=(v1e,v1o) .y=(v2e,v2o)
        ull s = fma2(Pv.x, qp0, fma2(Pv.y, qp1, mul2(Qv.x, qp2)));
        float se, so; up2(s, se, so);
        ull p = pk2(ex2f(se), ex2f(so));
        sum2 = add2(sum2, p);
        a02 = fma2(p, Qv.y, a02);
        a12 = fma2(p, Rv.x, a12);
        a22 = fma2(p, Rv.y, a22);
    }

    float sl, sh, c0l, c0h, c1l, c1h, c2l, c2h;
    up2(sum2, sl, sh); up2(a02, c0l, c0h); up2(a12, c1l, c1h); up2(a22, c2l, c2h);
    float cs = sl + sh, c0 = c0l + c0h, c1 = c1l + c1h, c2 = c2l + c2h;

    if ((q & 1) == 0) {                   // leftover single key j == q (even slot of pair np)
        const float* f = (const float*)sm;
        int base = 4 * np;
        float k0 = f[base + 0], k1 = f[base + 2];
        float k2 = f[4*NPAIR + base + 0], v0 = f[4*NPAIR + base + 2];
        float v1 = f[8*NPAIR + base + 0], v2 = f[8*NPAIR + base + 2];
        float s = fmaf(qv.x, k0, fmaf(qv.y, k1, qv.z * k2));
        float p = ex2f(s);
        cs += p; c0 = fmaf(p, v0, c0); c1 = fmaf(p, v1, c1); c2 = fmaf(p, v2, c2);
    }

    // ---- epilogue: out-proj rows 1,2 + 3x Euler + final velocity ----
    float inv = 1.0f / cs;
    float x0 = c0 * inv, x1 = c1 * inv, x2 = c2 * inv;
    float s1 = fmaf(wo[3], x0, fmaf(wo[4], x1, fmaf(wo[5], x2, bo1)));
    float s2 = fmaf(wo[6], x0, fmaf(wo[7], x1, fmaf(wo[8], x2, bo2)));

    float S2_1, S2_2, S3_1, S3_2, S4_1, S4_2;
    {
        float g1v = (G1[0] + fmaf(G1[1], s1, fmaf(G1[2], s2, G1b))) * m1;
        float g2v = (G2[0] + fmaf(G2[1], s1, fmaf(G2[2], s2, G2b))) * m2;
        S2_1 = fmaf(g1v, DT_C, s1); S2_2 = fmaf(g2v, DT_C, s2);
    }
    {
        float g1v = (G1[0] + fmaf(G1[1], S2_1, fmaf(G1[2], S2_2, G1b))) * m1;
        float g2v = (G2[0] + fmaf(G2[1], S2_1, fmaf(G2[2], S2_2, G2b))) * m2;
        S3_1 = fmaf(g1v, DT_C, S2_1); S3_2 = fmaf(g2v, DT_C, S2_2);
    }
    {
        float g1v = (G1[0] + fmaf(G1[1], S3_1, fmaf(G1[2], S3_2, G1b))) * m1;
        float g2v = (G2[0] + fmaf(G2[1], S3_1, fmaf(G2[2], S3_2, G2b))) * m2;
        S4_1 = fmaf(g1v, DT_C, S3_1); S4_2 = fmaf(g2v, DT_C, S3_2);
    }
    float vd1 = (F1[0] + fmaf(F1[1], S4_1, fmaf(F1[2], S4_2, F1b))) * m1;
    float vd2 = (F2[0] + fmaf(F2[1], S4_1, fmaf(F2[2], S4_2, F2b))) * m2;

    float4* o = (float4*)(out + (((size_t)b * LSEQ + q) << 3));
    o[0] = make_float4(S2_1 * sc0, S2_2 * sc1, S3_1 * sc0, S3_2 * sc1);
    o[1] = make_float4(S4_1 * sc0, S4_2 * sc1,
                       fmaf(vd1, DT_C, S4_1) * sc0, fmaf(vd2, DT_C, S4_2) * sc1);
}

extern "C" void kernel_launch(void* const* d_in, const int* in_sizes, int n_in,
                              void* d_out, int out_size)
{
    const float* inp = (const float*)d_in[1];
    const float* ipw = (const float*)d_in[2];
    const float* ipb = (const float*)d_in[3];
    const float* opw = (const float*)d_in[4];
    const float* opb = (const float*)d_in[5];
    const float* f1w = (const float*)d_in[6];
    const float* f1b = (const float*)d_in[7];
    const float* f2w = (const float*)d_in[8];
    const float* f2b = (const float*)d_in[9];
    const float* g1w = (const float*)d_in[10];
    const float* g1b = (const float*)d_in[11];
    const float* g2w = (const float*)d_in[12];
    const float* g2b = (const float*)d_in[13];
    const float* m1p = (const float*)d_in[14];
    const float* m2p = (const float*)d_in[15];
    const float* sig = (const float*)d_in[16];
    float* out = (float*)d_out;

    proj_kernel<<<(BATCH * NPAIR + 255) / 256, 256>>>(inp, ipw, ipb, sig);

    const int smem = 3 * NPAIR * sizeof(float4);   // 48 KB
    cudaFuncSetAttribute(attn_kernel, cudaFuncAttributeMaxDynamicSharedMemorySize, smem);
    dim3 grid(BATCH, NCHUNK2);
    attn_kernel<<<grid, TPB2, smem>>>(opw, opb, f1w, f1b, f2w, f2b,
                                      g1w, g1b, g2w, g2b, m1p, m2p, sig, out);
}